// round 2
// baseline (speedup 1.0000x reference)
#include <cuda_runtime.h>
#include <cuda_bf16.h>
#include <math.h>

// Problem constants
#define B_   16
#define C_   64
#define H_   160
#define W_   160
#define PD   32          // PDIM
#define HW   (H_*W_)     // 25600
#define LK_  13
#define PADK 6
#define TY   16
#define TX   16
#define ITH  (TY + 2*PADK)  // 28
#define ITW  (TX + 2*PADK)  // 28
#define FLT_STRIDE 34       // padded co-stride for [tap][co] filter slice (8B aligned, low conflicts)

typedef unsigned long long ull;

// ---------------- device scratch (no allocations allowed) ----------------
__device__ float g_gap[B_ * PD];        // 512
__device__ float g_dk[B_ * PD * 9];     // 4608

// ---------------- f32x2 packed helpers ----------------
__device__ __forceinline__ ull dup2(float a) {
    ull r;
    asm("mov.b64 %0, {%1, %1};" : "=l"(r) : "f"(a));
    return r;
}
__device__ __forceinline__ void fma2(ull& d, ull a, ull b) {
    asm("fma.rn.f32x2 %0, %1, %2, %0;" : "+l"(d) : "l"(a), "l"(b));
}
__device__ __forceinline__ float2 unpk(ull v) {
    float2 f;
    asm("mov.b64 {%0, %1}, %2;" : "=f"(f.x), "=f"(f.y) : "l"(v));
    return f;
}

// ---------------- kernel 1: global average pool over H,W for first 32 ch ----------------
__global__ void gap_kernel(const float* __restrict__ x) {
    int bc = blockIdx.x;           // 0..511  (b*32 + c)
    int b  = bc >> 5;
    int c  = bc & 31;
    const float4* p = (const float4*)(x + (size_t)(b * C_ + c) * HW);
    float s = 0.f;
    for (int i = threadIdx.x; i < HW / 4; i += 256) {
        float4 v = p[i];
        s += (v.x + v.y) + (v.z + v.w);
    }
    __shared__ float red[256];
    red[threadIdx.x] = s;
    __syncthreads();
    for (int st = 128; st > 0; st >>= 1) {
        if (threadIdx.x < st) red[threadIdx.x] += red[threadIdx.x + st];
        __syncthreads();
    }
    if (threadIdx.x == 0) g_gap[bc] = red[0] * (1.0f / (float)HW);
}

// ---------------- kernel 2: tiny MLP -> dynamic kernels dk[b][c][3][3] ----------------
__global__ void mlp_kernel(const float* __restrict__ w1, const float* __restrict__ b1,
                           const float* __restrict__ w2, const float* __restrict__ b2) {
    __shared__ float h[B_ * 16];   // 256
    int t = threadIdx.x;           // 288 threads
    if (t < 256) {
        int b = t >> 4, j = t & 15;
        float s = b1[j];
#pragma unroll
        for (int c = 0; c < 32; c++) s += g_gap[b * 32 + c] * w1[j * 32 + c];
        // exact gelu: 0.5*x*(1+erf(x/sqrt(2)))
        h[t] = 0.5f * s * (1.0f + erff(s * 0.7071067811865476f));
    }
    __syncthreads();
    for (int idx = t; idx < B_ * 288; idx += 288) {
        int b = idx / 288, k = idx % 288;
        float s = b2[k];
#pragma unroll
        for (int j = 0; j < 16; j++) s += h[b * 16 + j] * w2[k * 16 + j];
        g_dk[idx] = s;   // layout [b][c*9 + i*3 + j]
    }
}

// ---------------- kernel 3: passthrough copy of channels 32..63 ----------------
__global__ void copy_x2(const float4* __restrict__ src, float4* __restrict__ dst) {
    long long i = (long long)blockIdx.x * 256 + threadIdx.x;
    const long long per_b = (long long)PD * HW / 4;            // 204800
    if (i < (long long)B_ * per_b) {
        int b = (int)(i / per_b);
        long long r = i - (long long)b * per_b;
        size_t off = ((size_t)b * C_ + PD) * (HW / 4) + r;
        dst[off] = src[off];
    }
}

// ---------------- kernel 4: 13x13 dense conv (32->32) + fused dynamic 3x3 depthwise ----------------
// block: 256 threads = tx(16) x tz(4: co-group) x ty(4); each thread: 4 pixels x 8 co.
// grid: (10, 10, 16)
__global__ __launch_bounds__(256, 1)
void conv_main(const float* __restrict__ x, const float* __restrict__ flt,
               float* __restrict__ out) {
    extern __shared__ float sm[];
    float* sIn  = sm;                                   // 32 * 28*28 = 25088 floats
    float* sFlt = sm + PD * ITH * ITW;                  // 169 * 34 = 5746 floats
    float* sDk  = sFlt + 169 * FLT_STRIDE;              // 288 floats

    const int b  = blockIdx.z;
    const int x0 = blockIdx.x * TX;
    const int y0 = blockIdx.y * TY;
    const int tid = threadIdx.x;
    const int tx = tid & 15;
    const int tz = (tid >> 4) & 3;
    const int ty = tid >> 6;
    const int coB = tz * 8;

    // ---- load input tile (all 32 ci, halo 6, zero padded) ----
    const float* xb = x + (size_t)b * C_ * HW;
    for (int i = tid; i < PD * ITH * ITW; i += 256) {
        int ci = i / (ITH * ITW);
        int rem = i - ci * (ITH * ITW);
        int r = rem / ITW, c = rem - r * ITW;
        int gy = y0 - PADK + r, gx = x0 - PADK + c;
        float v = 0.f;
        if ((unsigned)gy < (unsigned)H_ && (unsigned)gx < (unsigned)W_)
            v = xb[ci * HW + gy * W_ + gx];
        sIn[i] = v;
    }
    for (int i = tid; i < PD * 9; i += 256) sDk[i] = g_dk[b * PD * 9 + i];

    ull acc[4][4];
#pragma unroll
    for (int p = 0; p < 4; p++)
#pragma unroll
        for (int q = 0; q < 4; q++) acc[p][q] = 0ULL;

    for (int ci = 0; ci < PD; ci++) {
        __syncthreads();   // first iter: input tile ready; later: compute done before overwrite
        // stage filter slice for this ci, transposed to [tap][co] with padded stride
        for (int i = tid; i < PD * 169; i += 256) {
            int co = i / 169, t = i - co * 169;
            sFlt[t * FLT_STRIDE + co] = flt[(size_t)(co * PD + ci) * 169 + t];
        }
        __syncthreads();

        const float* inC = sIn + ci * (ITH * ITW);
#pragma unroll 1
        for (int ky = 0; ky < LK_; ky++) {
            const float* r0 = inC + (ty * 4 + 0 + ky) * ITW + tx;
            const float* r1 = r0 + ITW;
            const float* r2 = r0 + 2 * ITW;
            const float* r3 = r0 + 3 * ITW;
            const float* wrow = sFlt + (ky * LK_) * FLT_STRIDE + coB;
#pragma unroll
            for (int kx = 0; kx < LK_; kx++) {
                const float* wp = wrow + kx * FLT_STRIDE;
                ull w0 = *(const ull*)(wp + 0);
                ull w1 = *(const ull*)(wp + 2);
                ull w2 = *(const ull*)(wp + 4);
                ull w3 = *(const ull*)(wp + 6);
                ull d0 = dup2(r0[kx]);
                ull d1 = dup2(r1[kx]);
                ull d2 = dup2(r2[kx]);
                ull d3 = dup2(r3[kx]);
                fma2(acc[0][0], d0, w0); fma2(acc[0][1], d0, w1);
                fma2(acc[0][2], d0, w2); fma2(acc[0][3], d0, w3);
                fma2(acc[1][0], d1, w0); fma2(acc[1][1], d1, w1);
                fma2(acc[1][2], d1, w2); fma2(acc[1][3], d1, w3);
                fma2(acc[2][0], d2, w0); fma2(acc[2][1], d2, w1);
                fma2(acc[2][2], d2, w2); fma2(acc[2][3], d2, w3);
                fma2(acc[3][0], d3, w0); fma2(acc[3][1], d3, w1);
                fma2(acc[3][2], d3, w2); fma2(acc[3][3], d3, w3);
            }
        }
    }

    // ---- epilogue: fused dynamic 3x3 depthwise conv + store ----
#pragma unroll
    for (int p = 0; p < 4; p++) {
        int ly = ty * 4 + p;
        int gy = y0 + ly;
#pragma unroll
        for (int q = 0; q < 4; q++) {
            float2 v = unpk(acc[p][q]);
            float rr[2] = {v.x, v.y};
#pragma unroll
            for (int s = 0; s < 2; s++) {
                int c = coB + 2 * q + s;
                const float* ib = sIn + c * (ITH * ITW) + (ly + PADK - 1) * ITW + (tx + PADK - 1);
                const float* kk = sDk + c * 9;
                float dv = ib[0]        * kk[0] + ib[1]        * kk[1] + ib[2]        * kk[2]
                         + ib[ITW]     * kk[3] + ib[ITW + 1]  * kk[4] + ib[ITW + 2]  * kk[5]
                         + ib[2 * ITW] * kk[6] + ib[2*ITW + 1]* kk[7] + ib[2*ITW + 2]* kk[8];
                out[(((size_t)b * C_ + c) * H_ + gy) * W_ + x0 + tx] = rr[s] + dv;
            }
        }
    }
}

// ---------------- launch ----------------
extern "C" void kernel_launch(void* const* d_in, const int* in_sizes, int n_in,
                              void* d_out, int out_size) {
    const float* x  = (const float*)d_in[0];
    const float* lk = (const float*)d_in[1];
    const float* w1 = (const float*)d_in[2];
    const float* b1 = (const float*)d_in[3];
    const float* w2 = (const float*)d_in[4];
    const float* b2 = (const float*)d_in[5];
    float* out = (float*)d_out;

    const int smem_bytes = (PD * ITH * ITW + 169 * FLT_STRIDE + PD * 9) * (int)sizeof(float); // 124488
    cudaFuncSetAttribute(conv_main, cudaFuncAttributeMaxDynamicSharedMemorySize, smem_bytes);

    gap_kernel<<<B_ * PD, 256>>>(x);
    mlp_kernel<<<1, 288>>>(w1, b1, w2, b2);

    // x2 passthrough: 3,276,800 float4
    copy_x2<<<(B_ * PD * HW / 4 + 255) / 256, 256>>>((const float4*)x, (float4*)out);

    dim3 grid(W_ / TX, H_ / TY, B_);
    conv_main<<<grid, 256, smem_bytes>>>(x, lk, out);
}

// round 3
// speedup vs baseline: 1.1940x; 1.1940x over previous
#include <cuda_runtime.h>
#include <cuda_bf16.h>
#include <math.h>

// Problem constants
#define B_   16
#define C_   64
#define H_   160
#define W_   160
#define PD   32
#define HW   (H_*W_)
#define LK_  13
#define PADK 6
#define TX   16          // tile width
#define TYR  32          // tile height (rows)
#define ITH  (TYR + 2*PADK)  // 44
#define ITW  (TX  + 2*PADK)  // 28
#define FSTRIDE 36           // filter [tap][co] stride: 16B aligned, co 0/16 offsets aligned
#define FSLICE  (169*FSTRIDE)  // 6084 floats per ci slice
#define IN_ELEMS (PD*ITH*ITW)  // 39424

typedef unsigned long long ull;

__device__ float g_gap[B_ * PD];
__device__ float g_dk[B_ * PD * 9];

// ---------------- packed f32x2 helpers ----------------
__device__ __forceinline__ ull dup2(float a) {
    ull r;
    asm("mov.b64 %0, {%1, %1};" : "=l"(r) : "f"(a));
    return r;
}
__device__ __forceinline__ void fma2(ull& d, ull a, ull b) {
    asm("fma.rn.f32x2 %0, %1, %2, %0;" : "+l"(d) : "l"(a), "l"(b));
}
__device__ __forceinline__ float2 unpk(ull v) {
    float2 f;
    asm("mov.b64 {%0, %1}, %2;" : "=f"(f.x), "=f"(f.y) : "l"(v));
    return f;
}
__device__ __forceinline__ void cp4(float* dst, const float* src) {
    unsigned d = (unsigned)__cvta_generic_to_shared(dst);
    asm volatile("cp.async.ca.shared.global [%0], [%1], 4;" :: "r"(d), "l"(src));
}

// ---------------- kernel 1: GAP over H,W for first 32 ch ----------------
__global__ void gap_kernel(const float* __restrict__ x) {
    int bc = blockIdx.x;
    int b  = bc >> 5;
    int c  = bc & 31;
    const float4* p = (const float4*)(x + (size_t)(b * C_ + c) * HW);
    float s = 0.f;
    for (int i = threadIdx.x; i < HW / 4; i += 256) {
        float4 v = p[i];
        s += (v.x + v.y) + (v.z + v.w);
    }
    __shared__ float red[256];
    red[threadIdx.x] = s;
    __syncthreads();
    for (int st = 128; st > 0; st >>= 1) {
        if (threadIdx.x < st) red[threadIdx.x] += red[threadIdx.x + st];
        __syncthreads();
    }
    if (threadIdx.x == 0) g_gap[bc] = red[0] * (1.0f / (float)HW);
}

// ---------------- kernel 2: tiny MLP -> dk[b][c][3][3] ----------------
__global__ void mlp_kernel(const float* __restrict__ w1, const float* __restrict__ b1,
                           const float* __restrict__ w2, const float* __restrict__ b2) {
    __shared__ float h[B_ * 16];
    int t = threadIdx.x;           // 288 threads
    if (t < 256) {
        int b = t >> 4, j = t & 15;
        float s = b1[j];
#pragma unroll
        for (int c = 0; c < 32; c++) s += g_gap[b * 32 + c] * w1[j * 32 + c];
        h[t] = 0.5f * s * (1.0f + erff(s * 0.7071067811865476f));
    }
    __syncthreads();
    for (int idx = t; idx < B_ * 288; idx += 288) {
        int b = idx / 288, k = idx % 288;
        float s = b2[k];
#pragma unroll
        for (int j = 0; j < 16; j++) s += h[b * 16 + j] * w2[k * 16 + j];
        g_dk[idx] = s;
    }
}

// ---------------- main: 13x13 conv (32->32) + fused dyn 3x3 dw + x2 copy ----------------
// block: 256 threads; tx = tid&15, ty = (tid>>4)&7, tz = tid>>7 (warp-uniform tz)
// each thread: 4 y-pixels x 16 co (32 f32x2 accumulators)
// grid: (10, 5, 16)
__global__ __launch_bounds__(256, 1)
void conv_main(const float* __restrict__ x, const float* __restrict__ flt,
               float* __restrict__ out) {
    extern __shared__ float sm[];
    float* sIn  = sm;                         // 39424 floats
    float* sFlt = sm + IN_ELEMS;              // 2 * 6084 floats (double buffered)
    float* sDk  = sFlt + 2 * FSLICE;          // 288 floats

    const int b   = blockIdx.z;
    const int x0  = blockIdx.x * TX;
    const int y0  = blockIdx.y * TYR;
    const int tid = threadIdx.x;
    const int tx  = tid & 15;
    const int ty  = (tid >> 4) & 7;
    const int tz  = tid >> 7;
    const int coB = tz * 16;
    const int ty4 = ty * 4;

    // ---- load input tile (32 ci, halo 6, zero padded) ----
    const float* xb = x + (size_t)b * C_ * HW;
    for (int i = tid; i < IN_ELEMS; i += 256) {
        int ci  = i / (ITH * ITW);
        int rem = i - ci * (ITH * ITW);
        int r = rem / ITW, c = rem - r * ITW;
        int gy = y0 - PADK + r, gx = x0 - PADK + c;
        float v = 0.f;
        if ((unsigned)gy < (unsigned)H_ && (unsigned)gx < (unsigned)W_)
            v = xb[ci * HW + gy * W_ + gx];
        sIn[i] = v;
    }
    for (int i = tid; i < PD * 9; i += 256) sDk[i] = g_dk[b * PD * 9 + i];

    // ---- stage filter slice ci=0 via cp.async (transposed to [tap][co]) ----
    {
        int co = tid >> 3, t0 = tid & 7;
        const float* src = flt + ((size_t)co * PD + 0) * 169;
        for (int t = t0; t < 169; t += 8) cp4(sFlt + t * FSTRIDE + co, src + t);
        asm volatile("cp.async.commit_group;" ::: "memory");
    }

    ull acc[4][8];
#pragma unroll
    for (int p = 0; p < 4; p++)
#pragma unroll
        for (int q = 0; q < 8; q++) acc[p][q] = 0ULL;

    for (int ci = 0; ci < PD; ci++) {
        asm volatile("cp.async.wait_group 0;" ::: "memory");
        __syncthreads();   // staged slice visible; prior reads of other buffer done
        if (ci + 1 < PD) {
            int co = tid >> 3, t0 = tid & 7;
            const float* src = flt + ((size_t)co * PD + ci + 1) * 169;
            float* dst = sFlt + ((ci + 1) & 1) * FSLICE;
            for (int t = t0; t < 169; t += 8) cp4(dst + t * FSTRIDE + co, src + t);
            asm volatile("cp.async.commit_group;" ::: "memory");
        }

        const float* fb  = sFlt + (ci & 1) * FSLICE;
        const float* inC = sIn + ci * (ITH * ITW);
#pragma unroll 1
        for (int ky = 0; ky < LK_; ky++) {
            const float* r0   = inC + (ty4 + ky) * ITW + tx;
            const float* wrow = fb + (ky * LK_) * FSTRIDE + coB;
#pragma unroll
            for (int kx = 0; kx < LK_; kx++) {
                const float* wp = wrow + kx * FSTRIDE;
                ulonglong2 pA = *(const ulonglong2*)(wp);       // co 0..3
                ulonglong2 pB = *(const ulonglong2*)(wp + 4);   // co 4..7
                ulonglong2 pC = *(const ulonglong2*)(wp + 8);   // co 8..11
                ulonglong2 pD = *(const ulonglong2*)(wp + 12);  // co 12..15
                ull d0 = dup2(r0[kx]);
                ull d1 = dup2(r0[kx + ITW]);
                ull d2 = dup2(r0[kx + 2 * ITW]);
                ull d3 = dup2(r0[kx + 3 * ITW]);
                fma2(acc[0][0], d0, pA.x); fma2(acc[0][1], d0, pA.y);
                fma2(acc[0][2], d0, pB.x); fma2(acc[0][3], d0, pB.y);
                fma2(acc[0][4], d0, pC.x); fma2(acc[0][5], d0, pC.y);
                fma2(acc[0][6], d0, pD.x); fma2(acc[0][7], d0, pD.y);
                fma2(acc[1][0], d1, pA.x); fma2(acc[1][1], d1, pA.y);
                fma2(acc[1][2], d1, pB.x); fma2(acc[1][3], d1, pB.y);
                fma2(acc[1][4], d1, pC.x); fma2(acc[1][5], d1, pC.y);
                fma2(acc[1][6], d1, pD.x); fma2(acc[1][7], d1, pD.y);
                fma2(acc[2][0], d2, pA.x); fma2(acc[2][1], d2, pA.y);
                fma2(acc[2][2], d2, pB.x); fma2(acc[2][3], d2, pB.y);
                fma2(acc[2][4], d2, pC.x); fma2(acc[2][5], d2, pC.y);
                fma2(acc[2][6], d2, pD.x); fma2(acc[2][7], d2, pD.y);
                fma2(acc[3][0], d3, pA.x); fma2(acc[3][1], d3, pA.y);
                fma2(acc[3][2], d3, pB.x); fma2(acc[3][3], d3, pB.y);
                fma2(acc[3][4], d3, pC.x); fma2(acc[3][5], d3, pC.y);
                fma2(acc[3][6], d3, pD.x); fma2(acc[3][7], d3, pD.y);
            }
        }
    }

    // ---- epilogue: fused dynamic 3x3 depthwise + store ----
#pragma unroll
    for (int p = 0; p < 4; p++) {
        int ly = ty4 + p;
        int gy = y0 + ly;
#pragma unroll
        for (int q = 0; q < 8; q++) {
            float2 v = unpk(acc[p][q]);
            float rr[2] = {v.x, v.y};
#pragma unroll
            for (int s = 0; s < 2; s++) {
                int c = coB + 2 * q + s;
                const float* ib = sIn + c * (ITH * ITW) + (ly + PADK - 1) * ITW + (tx + PADK - 1);
                const float* kk = sDk + c * 9;
                float dv = ib[0]          * kk[0] + ib[1]           * kk[1] + ib[2]           * kk[2]
                         + ib[ITW]        * kk[3] + ib[ITW + 1]     * kk[4] + ib[ITW + 2]     * kk[5]
                         + ib[2 * ITW]    * kk[6] + ib[2 * ITW + 1] * kk[7] + ib[2 * ITW + 2] * kk[8];
                out[(((size_t)b * C_ + c) * H_ + gy) * W_ + x0 + tx] = rr[s] + dv;
            }
        }
    }

    // ---- fused x2 passthrough copy for this tile (channels 32..63) ----
    for (int idx = tid; idx < PD * TYR * (TX / 4); idx += 256) {   // 4096 float4
        int ch2 = idx >> 7;
        int rem = idx & 127;
        int row = rem >> 2, c4 = rem & 3;
        size_t off = (((size_t)b * C_ + PD + ch2) * H_ + y0 + row) * W_ + x0 + c4 * 4;
        *(float4*)(out + off) = *(const float4*)(x + off);
    }
}

// ---------------- launch ----------------
extern "C" void kernel_launch(void* const* d_in, const int* in_sizes, int n_in,
                              void* d_out, int out_size) {
    const float* x  = (const float*)d_in[0];
    const float* lk = (const float*)d_in[1];
    const float* w1 = (const float*)d_in[2];
    const float* b1 = (const float*)d_in[3];
    const float* w2 = (const float*)d_in[4];
    const float* b2 = (const float*)d_in[5];
    float* out = (float*)d_out;

    const int smem_bytes = (IN_ELEMS + 2 * FSLICE + PD * 9) * (int)sizeof(float); // 207520
    cudaFuncSetAttribute(conv_main, cudaFuncAttributeMaxDynamicSharedMemorySize, smem_bytes);

    gap_kernel<<<B_ * PD, 256>>>(x);
    mlp_kernel<<<1, 288>>>(w1, b1, w2, b2);

    dim3 grid(W_ / TX, H_ / TYR, B_);
    conv_main<<<grid, 256, smem_bytes>>>(x, lk, out);
}